// round 1
// baseline (speedup 1.0000x reference)
#include <cuda_runtime.h>

#define D_MODEL 1024
#define N_HEADS 16
#define DK      64
#define B_SIZE  2
#define S_LEN   2048
#define M_ROWS  (B_SIZE * S_LEN)   // 4096

// ---------------- scratch (static device globals; no allocation) ----------------
__device__ float g_Qh[B_SIZE * N_HEADS * S_LEN * DK];   // [B,H,S,DK]
__device__ float g_Kh[B_SIZE * N_HEADS * S_LEN * DK];   // [B,H,S,DK] (holds Kh + k_pe)
__device__ float g_Vh[B_SIZE * N_HEADS * S_LEN * DK];   // [B,H,S,DK]
__device__ float g_attn[M_ROWS * D_MODEL];              // [B,S,D] attention output

// =====================================================================
// Projection GEMM: out = X @ W + bias, written head-split.
// Tile 64x64, BK=16, 256 threads, 4x4 micro-tile.
// z=0: Q (mode headsplit), z=1: K (headsplit + k_pe), z=2: V (headsplit)
// =====================================================================
__global__ __launch_bounds__(256) void proj_kernel(
    const float* __restrict__ q, const float* __restrict__ k, const float* __restrict__ v,
    const float* __restrict__ Wq, const float* __restrict__ Wk, const float* __restrict__ Wv,
    const float* __restrict__ bq, const float* __restrict__ bk, const float* __restrict__ bv,
    const float* __restrict__ kpe)
{
    __shared__ float As[16 * 68];   // As[k][m] transposed
    __shared__ float Bs[16 * 68];   // Bs[k][n]

    const int z = blockIdx.z;
    const float* X; const float* W; const float* bias; float* out;
    if (z == 0)      { X = q; W = Wq; bias = bq; out = g_Qh; }
    else if (z == 1) { X = k; W = Wk; bias = bk; out = g_Kh; }
    else             { X = v; W = Wv; bias = bv; out = g_Vh; }

    const int tid = threadIdx.x;
    const int tx = tid & 15, ty = tid >> 4;
    const int n0 = blockIdx.x * 64;
    const int m0 = blockIdx.y * 64;

    const int lrow = tid >> 2, lkq = tid & 3;    // X loader: 64 rows x 4 float4
    const int lk   = tid >> 4, lnq = tid & 15;   // W loader: 16 k x 16 float4

    float acc[4][4];
#pragma unroll
    for (int i = 0; i < 4; i++)
#pragma unroll
        for (int j = 0; j < 4; j++) acc[i][j] = 0.f;

    for (int k0 = 0; k0 < D_MODEL; k0 += 16) {
        __syncthreads();
        // load X tile transposed
        float4 xa = *(const float4*)&X[(size_t)(m0 + lrow) * D_MODEL + k0 + 4 * lkq];
        As[(4 * lkq + 0) * 68 + lrow] = xa.x;
        As[(4 * lkq + 1) * 68 + lrow] = xa.y;
        As[(4 * lkq + 2) * 68 + lrow] = xa.z;
        As[(4 * lkq + 3) * 68 + lrow] = xa.w;
        // load W tile
        *(float4*)&Bs[lk * 68 + 4 * lnq] =
            *(const float4*)&W[(size_t)(k0 + lk) * D_MODEL + n0 + 4 * lnq];
        __syncthreads();

#pragma unroll
        for (int kk = 0; kk < 16; kk++) {
            float4 a = *(float4*)&As[kk * 68 + 4 * ty];
            float4 b = *(float4*)&Bs[kk * 68 + 4 * tx];
            float av[4] = {a.x, a.y, a.z, a.w};
            float bv4[4] = {b.x, b.y, b.z, b.w};
#pragma unroll
            for (int i = 0; i < 4; i++)
#pragma unroll
                for (int j = 0; j < 4; j++) acc[i][j] += av[i] * bv4[j];
        }
    }

    // epilogue: head-split write
    float4 bia = *(const float4*)&bias[n0 + 4 * tx];
    const int h = n0 >> 6;           // whole block is one head (BN==DK==64)
    const int dbase = 4 * tx;
#pragma unroll
    for (int qi = 0; qi < 4; qi++) {
        int m = m0 + 4 * ty + qi;
        int b = m >> 11;             // /2048
        int s = m & 2047;
        float4 r;
        r.x = acc[qi][0] + bia.x;
        r.y = acc[qi][1] + bia.y;
        r.z = acc[qi][2] + bia.z;
        r.w = acc[qi][3] + bia.w;
        if (z == 1) {
            // Keff = Kh + k_pe[h, d, s]; k_pe shape [H, DK, S]
            r.x += kpe[(size_t)(h * DK + dbase + 0) * S_LEN + s];
            r.y += kpe[(size_t)(h * DK + dbase + 1) * S_LEN + s];
            r.z += kpe[(size_t)(h * DK + dbase + 2) * S_LEN + s];
            r.w += kpe[(size_t)(h * DK + dbase + 3) * S_LEN + s];
        }
        *(float4*)&out[(((size_t)b * N_HEADS + h) * S_LEN + s) * DK + dbase] = r;
    }
}

// =====================================================================
// Output projection GEMM: d_out = g_attn @ Wo + bo (plain layout)
// =====================================================================
__global__ __launch_bounds__(256) void outproj_kernel(
    const float* __restrict__ Wo, const float* __restrict__ bo, float* __restrict__ out)
{
    __shared__ float As[16 * 68];
    __shared__ float Bs[16 * 68];

    const int tid = threadIdx.x;
    const int tx = tid & 15, ty = tid >> 4;
    const int n0 = blockIdx.x * 64;
    const int m0 = blockIdx.y * 64;
    const int lrow = tid >> 2, lkq = tid & 3;
    const int lk   = tid >> 4, lnq = tid & 15;

    float acc[4][4];
#pragma unroll
    for (int i = 0; i < 4; i++)
#pragma unroll
        for (int j = 0; j < 4; j++) acc[i][j] = 0.f;

    for (int k0 = 0; k0 < D_MODEL; k0 += 16) {
        __syncthreads();
        float4 xa = *(const float4*)&g_attn[(size_t)(m0 + lrow) * D_MODEL + k0 + 4 * lkq];
        As[(4 * lkq + 0) * 68 + lrow] = xa.x;
        As[(4 * lkq + 1) * 68 + lrow] = xa.y;
        As[(4 * lkq + 2) * 68 + lrow] = xa.z;
        As[(4 * lkq + 3) * 68 + lrow] = xa.w;
        *(float4*)&Bs[lk * 68 + 4 * lnq] =
            *(const float4*)&Wo[(size_t)(k0 + lk) * D_MODEL + n0 + 4 * lnq];
        __syncthreads();

#pragma unroll
        for (int kk = 0; kk < 16; kk++) {
            float4 a = *(float4*)&As[kk * 68 + 4 * ty];
            float4 b = *(float4*)&Bs[kk * 68 + 4 * tx];
            float av[4] = {a.x, a.y, a.z, a.w};
            float bv4[4] = {b.x, b.y, b.z, b.w};
#pragma unroll
            for (int i = 0; i < 4; i++)
#pragma unroll
                for (int j = 0; j < 4; j++) acc[i][j] += av[i] * bv4[j];
        }
    }

    float4 bia = *(const float4*)&bo[n0 + 4 * tx];
#pragma unroll
    for (int qi = 0; qi < 4; qi++) {
        int m = m0 + 4 * ty + qi;
        float4 r;
        r.x = acc[qi][0] + bia.x;
        r.y = acc[qi][1] + bia.y;
        r.z = acc[qi][2] + bia.z;
        r.w = acc[qi][3] + bia.w;
        *(float4*)&out[(size_t)m * D_MODEL + n0 + 4 * tx] = r;
    }
}

// =====================================================================
// Flash attention, fp32. Block = 64 queries x one (b,h). 256 threads.
// Smem (dynamic, ~53KB): Qt[d][q], KVt (Kt[d][t] then Vs[t][d]), Pt[t][q], m/l/corr
// =====================================================================
#define PAD 68
#define ATTN_SMEM_BYTES ((3 * 64 * PAD + 3 * 64) * 4)

__global__ __launch_bounds__(256) void attn_kernel()
{
    extern __shared__ float sm[];
    float* Qt  = sm;                 // [64][PAD]  Qt[d][q], pre-scaled by 1/8
    float* KVt = sm + 64 * PAD;      // [64][PAD]  Kt[d][t] then Vs[t][d]
    float* Pt  = sm + 2 * 64 * PAD;  // [64][PAD]  Pt[t][q]
    float* mrow = sm + 3 * 64 * PAD; // [64]
    float* lrow = mrow + 64;         // [64]
    float* crow = lrow + 64;         // [64]

    const int tid = threadIdx.x;
    const int tx = tid & 15, ty = tid >> 4;
    const int q0 = blockIdx.x * 64;
    const int h = blockIdx.y;
    const int b = blockIdx.z;

    const float* Qbase = g_Qh + (((size_t)b * N_HEADS + h) * S_LEN + q0) * DK;
    const float* Kbase = g_Kh + (((size_t)b * N_HEADS + h) * S_LEN) * DK;
    const float* Vbase = g_Vh + (((size_t)b * N_HEADS + h) * S_LEN) * DK;

    // load Q tile transposed, scaled by 1/sqrt(dk)=0.125
#pragma unroll
    for (int i = 0; i < 16; i++) {
        int idx = tid + i * 256;
        int s = idx >> 6, d = idx & 63;
        Qt[d * PAD + s] = Qbase[s * DK + d] * 0.125f;
    }
    if (tid < 64) { mrow[tid] = -1e30f; lrow[tid] = 0.f; }

    float acc[4][4];
#pragma unroll
    for (int i = 0; i < 4; i++)
#pragma unroll
        for (int j = 0; j < 4; j++) acc[i][j] = 0.f;

    __syncthreads();

    for (int t0 = 0; t0 < S_LEN; t0 += 64) {
        // 1) K tile transposed into KVt
#pragma unroll
        for (int i = 0; i < 16; i++) {
            int idx = tid + i * 256;
            int t = idx >> 6, d = idx & 63;
            KVt[d * PAD + t] = Kbase[(size_t)(t0 + t) * DK + d];
        }
        __syncthreads();

        // 2) scores S = Q*K^T (4x4 micro-tile, contract d)
        float sc[4][4];
#pragma unroll
        for (int i = 0; i < 4; i++)
#pragma unroll
            for (int j = 0; j < 4; j++) sc[i][j] = 0.f;
#pragma unroll
        for (int d = 0; d < 64; d++) {
            float4 a = *(float4*)&Qt[d * PAD + 4 * ty];
            float4 bb = *(float4*)&KVt[d * PAD + 4 * tx];
            float av[4] = {a.x, a.y, a.z, a.w};
            float bv4[4] = {bb.x, bb.y, bb.z, bb.w};
#pragma unroll
            for (int i = 0; i < 4; i++)
#pragma unroll
                for (int j = 0; j < 4; j++) sc[i][j] += av[i] * bv4[j];
        }
        // write raw scores Pt[t][q]
#pragma unroll
        for (int tj = 0; tj < 4; tj++)
#pragma unroll
            for (int qi = 0; qi < 4; qi++)
                Pt[(4 * tx + tj) * PAD + 4 * ty + qi] = sc[qi][tj];
        __syncthreads();

        // 3) online softmax (q-owner: 4 threads per query) + V load
        {
            const int qq = tid >> 2, l4 = tid & 3;
            float mloc = -1e30f;
#pragma unroll
            for (int i = 0; i < 16; i++) {
                float sv = Pt[(l4 * 16 + i) * PAD + qq];
                mloc = fmaxf(mloc, sv);
            }
            mloc = fmaxf(mloc, __shfl_xor_sync(0xffffffffu, mloc, 1));
            mloc = fmaxf(mloc, __shfl_xor_sync(0xffffffffu, mloc, 2));
            float mold = mrow[qq];
            float mnew = fmaxf(mold, mloc);
            float corr = __expf(mold - mnew);
            float lsum = 0.f;
#pragma unroll
            for (int i = 0; i < 16; i++) {
                float sv = Pt[(l4 * 16 + i) * PAD + qq];
                float p = __expf(sv - mnew);
                Pt[(l4 * 16 + i) * PAD + qq] = p;
                lsum += p;
            }
            lsum += __shfl_xor_sync(0xffffffffu, lsum, 1);
            lsum += __shfl_xor_sync(0xffffffffu, lsum, 2);
            if (l4 == 0) {
                lrow[qq] = lrow[qq] * corr + lsum;
                mrow[qq] = mnew;
                crow[qq] = corr;
            }
            // V tile (natural layout) into KVt
#pragma unroll
            for (int i = 0; i < 16; i++) {
                int idx = tid + i * 256;
                int t = idx >> 6, d = idx & 63;
                KVt[t * PAD + d] = Vbase[(size_t)(t0 + t) * DK + d];
            }
        }
        __syncthreads();

        // 4) rescale accumulators, accumulate P @ V (4x4 micro-tile, contract t)
        float cf[4];
#pragma unroll
        for (int qi = 0; qi < 4; qi++) cf[qi] = crow[4 * ty + qi];
#pragma unroll
        for (int qi = 0; qi < 4; qi++)
#pragma unroll
            for (int j = 0; j < 4; j++) acc[qi][j] *= cf[qi];
#pragma unroll
        for (int t = 0; t < 64; t++) {
            float4 p = *(float4*)&Pt[t * PAD + 4 * ty];
            float4 vv = *(float4*)&KVt[t * PAD + 4 * tx];
            float pv[4] = {p.x, p.y, p.z, p.w};
            float vv4[4] = {vv.x, vv.y, vv.z, vv.w};
#pragma unroll
            for (int qi = 0; qi < 4; qi++)
#pragma unroll
                for (int j = 0; j < 4; j++) acc[qi][j] += pv[qi] * vv4[j];
        }
        __syncthreads();
    }

    // epilogue: normalize and write to g_attn [B,S,D] with column block h*64
#pragma unroll
    for (int qi = 0; qi < 4; qi++) {
        int s = q0 + 4 * ty + qi;
        float inv = 1.f / lrow[4 * ty + qi];
        float4 r;
        r.x = acc[qi][0] * inv;
        r.y = acc[qi][1] * inv;
        r.z = acc[qi][2] * inv;
        r.w = acc[qi][3] * inv;
        *(float4*)&g_attn[((size_t)b * S_LEN + s) * D_MODEL + h * DK + 4 * tx] = r;
    }
}

// =====================================================================
extern "C" void kernel_launch(void* const* d_in, const int* in_sizes, int n_in,
                              void* d_out, int out_size)
{
    const float* q   = (const float*)d_in[0];
    const float* k   = (const float*)d_in[1];
    const float* v   = (const float*)d_in[2];
    const float* kpe = (const float*)d_in[3];
    const float* Wq  = (const float*)d_in[4];
    const float* bq  = (const float*)d_in[5];
    const float* Wk  = (const float*)d_in[6];
    const float* bk  = (const float*)d_in[7];
    const float* Wv  = (const float*)d_in[8];
    const float* bv  = (const float*)d_in[9];
    const float* Wo  = (const float*)d_in[10];
    const float* bo  = (const float*)d_in[11];
    float* out = (float*)d_out;

    // attention kernel needs >48KB dynamic smem
    cudaFuncSetAttribute(attn_kernel, cudaFuncAttributeMaxDynamicSharedMemorySize,
                         ATTN_SMEM_BYTES);

    dim3 gp(D_MODEL / 64, M_ROWS / 64, 3);
    proj_kernel<<<gp, 256>>>(q, k, v, Wq, Wk, Wv, bq, bk, bv, kpe);

    dim3 ga(S_LEN / 64, N_HEADS, B_SIZE);
    attn_kernel<<<ga, 256, ATTN_SMEM_BYTES>>>();

    dim3 go(D_MODEL / 64, M_ROWS / 64, 1);
    outproj_kernel<<<go, 256>>>(Wo, bo, out);
}